// round 16
// baseline (speedup 1.0000x reference)
#include <cuda_runtime.h>
#include <cstdint>

#define NN      100000
#define NE      1600000
#define HID     16
#define OUTD    40
#define QMAXF   255.0f

#define SPMM_BLOCKS 1184   // R9 measured-best

// ---------------------------------------------------------------------------
// Scratch (device globals — allocation is forbidden)
// ---------------------------------------------------------------------------
__device__ __align__(16) float g_ya[NN * HID];
__device__ __align__(16) float g_yb[NN * HID];
__device__ __align__(16) int2 g_ecv[NE];   // row-sorted (col, val-bits)
__device__ int   g_cnt[NN];
__device__ int   g_cur[NN];
__device__ int   g_off[NN + 1];
__device__ int   g_bsum[128];

// ---------------------------------------------------------------------------
// CSR build: memset(cnt) -> hist -> scan1 -> scan3 -> scatter  (PDL-chained)
// ---------------------------------------------------------------------------
__global__ void __launch_bounds__(256) k_hist(const int* __restrict__ row) {
    int e = blockIdx.x * 256 + threadIdx.x;
    if (e < NE) atomicAdd(&g_cnt[__ldg(&row[e])], 1);
}

__global__ void __launch_bounds__(256) k_scan1() {
#if __CUDA_ARCH__ >= 900
    cudaGridDependencySynchronize();     // wait for hist's g_cnt
#endif
    int b = blockIdx.x, t = threadIdx.x;
    int base = b * 1024 + t * 4;
    int s = 0;
#pragma unroll
    for (int i = 0; i < 4; i++) { int idx = base + i; if (idx < NN) s += g_cnt[idx]; }
    __shared__ int sh[256];
    sh[t] = s; __syncthreads();
#pragma unroll
    for (int o = 128; o > 0; o >>= 1) {
        if (t < o) sh[t] += sh[t + o];
        __syncthreads();
    }
    if (t == 0) g_bsum[b] = sh[0];
}

__global__ void __launch_bounds__(256) k_scan3() {
#if __CUDA_ARCH__ >= 900
    cudaGridDependencySynchronize();     // wait for scan1 (transitively hist)
#endif
    int b = blockIdx.x, t = threadIdx.x;
    int base = b * 1024 + t * 4;
    int c[4]; int tot = 0;
#pragma unroll
    for (int i = 0; i < 4; i++) {
        int idx = base + i;
        c[i] = (idx < NN) ? g_cnt[idx] : 0;
        tot += c[i];
    }
    __shared__ int sh[256];
    sh[t] = tot; __syncthreads();
#pragma unroll
    for (int o = 1; o < 256; o <<= 1) {
        int u = (t >= o) ? sh[t - o] : 0;
        __syncthreads();
        sh[t] += u;
        __syncthreads();
    }
    const int exclThread = sh[t] - tot;
    __syncthreads();

    sh[t] = (t < b) ? g_bsum[t] : 0;
    __syncthreads();
#pragma unroll
    for (int o = 128; o > 0; o >>= 1) {
        if (t < o) sh[t] += sh[t + o];
        __syncthreads();
    }
    int run = sh[0] + exclThread;
#pragma unroll
    for (int i = 0; i < 4; i++) {
        int idx = base + i;
        if (idx < NN) { g_off[idx] = run; g_cur[idx] = run; run += c[i]; }
    }
    if (b == 0 && t == 0) g_off[NN] = NE;
}

// Scatter with PDL preamble: row/col/vals are kernel inputs (independent of
// scan3) -> prefetch into registers BEFORE the gridsync; only the g_cur
// atomic + g_ecv store depend on scan3.
__global__ void __launch_bounds__(256) k_scatter(
    const int* __restrict__ row, const int* __restrict__ col,
    const float* __restrict__ vals)
{
    int e = blockIdx.x * 256 + threadIdx.x;
    int   r = 0, c = 0; float v = 0.f;
    const bool live = (e < NE);
    if (live) {
        r = __ldg(&row[e]);
        c = __ldg(&col[e]);
        v = __ldg(&vals[e]);
    }
#if __CUDA_ARCH__ >= 900
    cudaGridDependencySynchronize();     // wait for scan3's g_cur/g_off
#endif
    if (live) {
        int p = atomicAdd(&g_cur[r], 1);
        g_ecv[p] = make_int2(c, __float_as_int(v));
    }
}

// ---------------------------------------------------------------------------
// Layer 1: per-row (128-dim) qdq fused with x @ W1 -> y [N,16]. Warp per row.
// ---------------------------------------------------------------------------
template<int OFF, int V>
__device__ __forceinline__ void reduce_stage(float* acc, int lane) {
    const bool hi = (lane & OFF) != 0;
    float out[V];
#pragma unroll
    for (int m = 0; m < V; m++) {
        float keep = hi ? acc[m + V] : acc[m];
        float send = hi ? acc[m]     : acc[m + V];
        out[m] = keep + __shfl_xor_sync(0xffffffffu, send, OFF);
    }
#pragma unroll
    for (int m = 0; m < V; m++) acc[m] = out[m];
}

__global__ void __launch_bounds__(128) k_layer1(
    const float* __restrict__ x, const float* __restrict__ noise,
    const float* __restrict__ W1, float* __restrict__ y)
{
    const int lane   = threadIdx.x & 31;
    const int warpId = (blockIdx.x * (blockDim.x >> 5)) + (threadIdx.x >> 5);
    const int nWarp  = gridDim.x * (blockDim.x >> 5);

    float4 w[16];
    const float4* W4 = (const float4*)W1;
#pragma unroll
    for (int i = 0; i < 4; i++)
#pragma unroll
        for (int jj = 0; jj < 4; jj++)
            w[i * 4 + jj] = __ldg(&W4[(lane * 4 + i) * 4 + jj]);

    for (int r = warpId; r < NN; r += nWarp) {
        float4 xv = __ldg(&((const float4*)x)[r * 32 + lane]);
        float4 nv = __ldg(&((const float4*)noise)[r * 32 + lane]);
        float xa[4] = {xv.x, xv.y, xv.z, xv.w};
        float na[4] = {nv.x, nv.y, nv.z, nv.w};

        float mn = fminf(fminf(xa[0], xa[1]), fminf(xa[2], xa[3]));
        float mx = fmaxf(fmaxf(xa[0], xa[1]), fmaxf(xa[2], xa[3]));
#pragma unroll
        for (int off = 16; off > 0; off >>= 1) {
            mn = fminf(mn, __shfl_xor_sync(0xffffffffu, mn, off));
            mx = fmaxf(mx, __shfl_xor_sync(0xffffffffu, mx, off));
        }

        float dq[4];
        if (mx > mn) {
            float rs = QMAXF / (mx - mn);
#pragma unroll
            for (int i = 0; i < 4; i++) {
                float q = rintf((xa[i] - mn) * rs + na[i] - 0.5f);
                q = fminf(fmaxf(q, 0.f), QMAXF);
                dq[i] = q / rs + mn;
            }
        } else {
#pragma unroll
            for (int i = 0; i < 4; i++) dq[i] = mn;
        }

        float acc[16];
#pragma unroll
        for (int j = 0; j < 16; j++) acc[j] = 0.f;
#pragma unroll
        for (int i = 0; i < 4; i++) {
#pragma unroll
            for (int jj = 0; jj < 4; jj++) {
                float4 ww = w[i * 4 + jj];
                acc[jj * 4 + 0] = fmaf(dq[i], ww.x, acc[jj * 4 + 0]);
                acc[jj * 4 + 1] = fmaf(dq[i], ww.y, acc[jj * 4 + 1]);
                acc[jj * 4 + 2] = fmaf(dq[i], ww.z, acc[jj * 4 + 2]);
                acc[jj * 4 + 3] = fmaf(dq[i], ww.w, acc[jj * 4 + 3]);
            }
        }
        reduce_stage<16, 8>(acc, lane);
        reduce_stage<8, 4>(acc, lane);
        reduce_stage<4, 2>(acc, lane);
        reduce_stage<2, 1>(acc, lane);
        float s = acc[0] + __shfl_xor_sync(0xffffffffu, acc[0], 1);
        if ((lane & 1) == 0)
            y[r * 16 + ((lane >> 1) & 15)] = s;
    }
}

// ---------------------------------------------------------------------------
// CSR row-gather SpMM (R9 measured-best) with PDL: preamble (Ws load) runs
// BEFORE cudaGridDependencySynchronize(); all dependent reads after it.
//   EP=1: relu+qdq+@W(16x16) -> y    EP=2: relu+qdq -> y    EP=3: @W3 -> out
// ---------------------------------------------------------------------------
template<int EP>
__global__ void __launch_bounds__(256) k_spmm(
    const float* __restrict__ yin, const float* __restrict__ noise,
    const float* __restrict__ W, float* __restrict__ out)
{
    __shared__ float Ws[16 * 40];
    if (EP == 1) Ws[threadIdx.x] = W[threadIdx.x];
    if (EP == 3) { for (int i = threadIdx.x; i < 640; i += 256) Ws[i] = W[i]; }
    if (EP != 2) __syncthreads();

#if __CUDA_ARCH__ >= 900
    cudaGridDependencySynchronize();     // wait for predecessor's output
#endif

    const int lane  = threadIdx.x & 31;
    const int l     = lane & 15;                       // dim index
    const int half0 = (blockIdx.x * 8 + (threadIdx.x >> 5)) * 2 + (lane >> 4);
    const int nHalf = SPMM_BLOCKS * 16;

    for (int r = half0; r < NN; r += nHalf) {
        int       i = __ldg(&g_off[r]);
        const int e = __ldg(&g_off[r + 1]);
        float acc = 0.f;

        for (; i + 3 < e; i += 4) {
            int2 c0 = __ldg(&g_ecv[i]);
            int2 c1 = __ldg(&g_ecv[i + 1]);
            int2 c2 = __ldg(&g_ecv[i + 2]);
            int2 c3 = __ldg(&g_ecv[i + 3]);
            float y0 = __ldg(&yin[c0.x * 16 + l]);
            float y1 = __ldg(&yin[c1.x * 16 + l]);
            float y2 = __ldg(&yin[c2.x * 16 + l]);
            float y3 = __ldg(&yin[c3.x * 16 + l]);
            acc = fmaf(__int_as_float(c0.y), y0, acc);
            acc = fmaf(__int_as_float(c1.y), y1, acc);
            acc = fmaf(__int_as_float(c2.y), y2, acc);
            acc = fmaf(__int_as_float(c3.y), y3, acc);
        }
        for (; i < e; i++) {
            int2 cv = __ldg(&g_ecv[i]);
            acc = fmaf(__int_as_float(cv.y), __ldg(&yin[cv.x * 16 + l]), acc);
        }

        if (EP == 3) {
            float a0 = 0.f, a1 = 0.f, a2 = 0.f;
#pragma unroll
            for (int j = 0; j < 16; j++) {
                float d = __shfl_sync(0xffffffffu, acc, (lane & 16) + j);
                a0 = fmaf(d, Ws[j * 40 + l], a0);
                a1 = fmaf(d, Ws[j * 40 + l + 16], a1);
                if (l < 8) a2 = fmaf(d, Ws[j * 40 + l + 32], a2);
            }
            out[r * 40 + l]      = a0;
            out[r * 40 + l + 16] = a1;
            if (l < 8) out[r * 40 + l + 32] = a2;
        } else {
            float xr = fmaxf(acc, 0.f);
            float mn = xr, mx = xr;
#pragma unroll
            for (int o = 8; o > 0; o >>= 1) {
                mn = fminf(mn, __shfl_xor_sync(0xffffffffu, mn, o));
                mx = fmaxf(mx, __shfl_xor_sync(0xffffffffu, mx, o));
            }
            float dq;
            if (mx > mn) {
                float rs = QMAXF / (mx - mn);
                float nz = __ldg(&noise[r * 16 + l]);
                float q  = rintf((xr - mn) * rs + nz - 0.5f);
                q = fminf(fmaxf(q, 0.f), QMAXF);
                dq = q / rs + mn;
            } else dq = mn;

            if (EP == 2) {
                out[r * 16 + l] = dq;
            } else {
                float a = 0.f;
#pragma unroll
                for (int j = 0; j < 16; j++) {
                    float d = __shfl_sync(0xffffffffu, dq, (lane & 16) + j);
                    a = fmaf(d, Ws[j * 16 + l], a);
                }
                out[r * 16 + l] = a;
            }
        }
    }
}

// ---------------------------------------------------------------------------
// Launch: fork/join (layer1 on side stream) + PDL on build chain and SpMMs.
// ---------------------------------------------------------------------------
extern "C" void kernel_launch(void* const* d_in, const int* in_sizes, int n_in,
                              void* d_out, int out_size)
{
    const float* features = (const float*)d_in[0];
    const int*   row      = (const int*)  d_in[1];
    const int*   col      = (const int*)  d_in[2];
    const float* vals     = (const float*)d_in[3];
    const float* W1       = (const float*)d_in[4];
    const float* W2       = (const float*)d_in[5];
    const float* W3       = (const float*)d_in[6];
    const float* noise1   = (const float*)d_in[7];
    const float* noise2   = (const float*)d_in[8];
    const float* noise3   = (const float*)d_in[9];

    float *pya, *pyb; int* pcnt;
    cudaGetSymbolAddress((void**)&pya,  g_ya);
    cudaGetSymbolAddress((void**)&pyb,  g_yb);
    cudaGetSymbolAddress((void**)&pcnt, g_cnt);

    const int edgeBlocks = (NE + 255) / 256;     // 6250
    const int scanBlocks = (NN + 1023) / 1024;   // 98

    cudaStream_t s2;
    cudaEvent_t evFork, evJoin;
    cudaStreamCreateWithFlags(&s2, cudaStreamNonBlocking);
    cudaEventCreateWithFlags(&evFork, cudaEventDisableTiming);
    cudaEventCreateWithFlags(&evJoin, cudaEventDisableTiming);

    // Fork: layer1 runs parallel to the CSR build chain.
    cudaEventRecord(evFork, 0);
    cudaStreamWaitEvent(s2, evFork, 0);
    k_layer1<<<740, 128, 0, s2>>>(features, noise1, W1, pya);
    cudaEventRecord(evJoin, s2);

    // PDL launch config helper.
    cudaLaunchAttribute pdlAttr[1];
    pdlAttr[0].id = cudaLaunchAttributeProgrammaticStreamSerialization;
    pdlAttr[0].val.programmaticStreamSerializationAllowed = 1;

    cudaLaunchConfig_t cfg = {};
    cfg.blockDim = dim3(256, 1, 1);
    cfg.dynamicSmemBytes = 0;
    cfg.stream = 0;
    cfg.attrs = pdlAttr;
    cfg.numAttrs = 1;

    // CSR build (default stream). hist = plain launch (after memset node);
    // scan1/scan3/scatter PDL-chained.
    cudaMemsetAsync(pcnt, 0, NN * sizeof(int));
    k_hist<<<edgeBlocks, 256>>>(row);

    cfg.gridDim = dim3(scanBlocks, 1, 1);
    cudaLaunchKernelEx(&cfg, k_scan1);
    cudaLaunchKernelEx(&cfg, k_scan3);

    cfg.gridDim = dim3(edgeBlocks, 1, 1);
    cudaLaunchKernelEx(&cfg, k_scatter, row, col, vals);

    // Join: spmm<1> needs both layer1 output and the CSR.
    cudaStreamWaitEvent(0, evJoin, 0);

    // SpMM pipeline with PDL.
    cfg.gridDim = dim3(SPMM_BLOCKS, 1, 1);
    cudaLaunchKernelEx(&cfg, k_spmm<1>, pya, noise2, W2, pyb);
    cudaLaunchKernelEx(&cfg, k_spmm<2>, pyb, noise3, (const float*)nullptr, pya);
    cudaLaunchKernelEx(&cfg, k_spmm<3>, pya, (const float*)nullptr, W3, (float*)d_out);
}

// round 17
// speedup vs baseline: 1.0022x; 1.0022x over previous
#include <cuda_runtime.h>
#include <cstdint>

#define NN      100000
#define NE      1600000
#define HID     16
#define OUTD    40
#define QMAXF   255.0f

#define SPMM_BLOCKS 1184   // R9 measured-best

// ---------------------------------------------------------------------------
// Scratch (device globals — allocation is forbidden)
// ---------------------------------------------------------------------------
__device__ __align__(16) float g_ya[NN * HID];
__device__ __align__(16) float g_yb[NN * HID];
__device__ __align__(16) int2 g_ecv[NE];   // row-sorted (col, val-bits)
__device__ int   g_rank[NE];               // edge rank within its row (from hist)
__device__ int   g_cnt[NN];
__device__ int   g_off[NN + 1];
__device__ int   g_bsum[128];

// ---------------------------------------------------------------------------
// CSR build: memset(cnt) -> hist(+rank) -> scan1 -> scan3 -> scatter(no atomics)
// ---------------------------------------------------------------------------
__global__ void __launch_bounds__(256) k_hist(const int* __restrict__ row) {
    int e = blockIdx.x * 256 + threadIdx.x;
    if (e < NE)
        g_rank[e] = atomicAdd(&g_cnt[__ldg(&row[e])], 1);
}

__global__ void __launch_bounds__(256) k_scan1() {
#if __CUDA_ARCH__ >= 900
    cudaGridDependencySynchronize();     // wait for hist's g_cnt
#endif
    int b = blockIdx.x, t = threadIdx.x;
    int base = b * 1024 + t * 4;
    int s = 0;
#pragma unroll
    for (int i = 0; i < 4; i++) { int idx = base + i; if (idx < NN) s += g_cnt[idx]; }
    __shared__ int sh[256];
    sh[t] = s; __syncthreads();
#pragma unroll
    for (int o = 128; o > 0; o >>= 1) {
        if (t < o) sh[t] += sh[t + o];
        __syncthreads();
    }
    if (t == 0) g_bsum[b] = sh[0];
}

__global__ void __launch_bounds__(256) k_scan3() {
#if __CUDA_ARCH__ >= 900
    cudaGridDependencySynchronize();     // wait for scan1 (transitively hist)
#endif
    int b = blockIdx.x, t = threadIdx.x;
    int base = b * 1024 + t * 4;
    int c[4]; int tot = 0;
#pragma unroll
    for (int i = 0; i < 4; i++) {
        int idx = base + i;
        c[i] = (idx < NN) ? g_cnt[idx] : 0;
        tot += c[i];
    }
    __shared__ int sh[256];
    sh[t] = tot; __syncthreads();
#pragma unroll
    for (int o = 1; o < 256; o <<= 1) {
        int u = (t >= o) ? sh[t - o] : 0;
        __syncthreads();
        sh[t] += u;
        __syncthreads();
    }
    const int exclThread = sh[t] - tot;
    __syncthreads();

    sh[t] = (t < b) ? g_bsum[t] : 0;
    __syncthreads();
#pragma unroll
    for (int o = 128; o > 0; o >>= 1) {
        if (t < o) sh[t] += sh[t + o];
        __syncthreads();
    }
    int run = sh[0] + exclThread;
#pragma unroll
    for (int i = 0; i < 4; i++) {
        int idx = base + i;
        if (idx < NN) { g_off[idx] = run; run += c[i]; }
    }
    if (b == 0 && t == 0) g_off[NN] = NE;
}

// Atomic-free scatter: slot = g_off[row[e]] + rank[e]. row/col/vals (kernel
// inputs) prefetched before the gridsync; g_off (scan3) and g_rank (hist,
// complete transitively) read after it.
__global__ void __launch_bounds__(256) k_scatter(
    const int* __restrict__ row, const int* __restrict__ col,
    const float* __restrict__ vals)
{
    int e = blockIdx.x * 256 + threadIdx.x;
    int   r = 0, c = 0; float v = 0.f;
    const bool live = (e < NE);
    if (live) {
        r = __ldg(&row[e]);
        c = __ldg(&col[e]);
        v = __ldg(&vals[e]);
    }
#if __CUDA_ARCH__ >= 900
    cudaGridDependencySynchronize();     // wait for scan3's g_off
#endif
    if (live) {
        int p = __ldg(&g_off[r]) + __ldg(&g_rank[e]);
        g_ecv[p] = make_int2(c, __float_as_int(v));
    }
}

// ---------------------------------------------------------------------------
// Layer 1: per-row (128-dim) qdq fused with x @ W1 -> y [N,16]. Warp per row.
// ---------------------------------------------------------------------------
template<int OFF, int V>
__device__ __forceinline__ void reduce_stage(float* acc, int lane) {
    const bool hi = (lane & OFF) != 0;
    float out[V];
#pragma unroll
    for (int m = 0; m < V; m++) {
        float keep = hi ? acc[m + V] : acc[m];
        float send = hi ? acc[m]     : acc[m + V];
        out[m] = keep + __shfl_xor_sync(0xffffffffu, send, OFF);
    }
#pragma unroll
    for (int m = 0; m < V; m++) acc[m] = out[m];
}

__global__ void __launch_bounds__(128) k_layer1(
    const float* __restrict__ x, const float* __restrict__ noise,
    const float* __restrict__ W1, float* __restrict__ y)
{
    const int lane   = threadIdx.x & 31;
    const int warpId = (blockIdx.x * (blockDim.x >> 5)) + (threadIdx.x >> 5);
    const int nWarp  = gridDim.x * (blockDim.x >> 5);

    float4 w[16];
    const float4* W4 = (const float4*)W1;
#pragma unroll
    for (int i = 0; i < 4; i++)
#pragma unroll
        for (int jj = 0; jj < 4; jj++)
            w[i * 4 + jj] = __ldg(&W4[(lane * 4 + i) * 4 + jj]);

    for (int r = warpId; r < NN; r += nWarp) {
        float4 xv = __ldg(&((const float4*)x)[r * 32 + lane]);
        float4 nv = __ldg(&((const float4*)noise)[r * 32 + lane]);
        float xa[4] = {xv.x, xv.y, xv.z, xv.w};
        float na[4] = {nv.x, nv.y, nv.z, nv.w};

        float mn = fminf(fminf(xa[0], xa[1]), fminf(xa[2], xa[3]));
        float mx = fmaxf(fmaxf(xa[0], xa[1]), fmaxf(xa[2], xa[3]));
#pragma unroll
        for (int off = 16; off > 0; off >>= 1) {
            mn = fminf(mn, __shfl_xor_sync(0xffffffffu, mn, off));
            mx = fmaxf(mx, __shfl_xor_sync(0xffffffffu, mx, off));
        }

        float dq[4];
        if (mx > mn) {
            float rs = QMAXF / (mx - mn);
#pragma unroll
            for (int i = 0; i < 4; i++) {
                float q = rintf((xa[i] - mn) * rs + na[i] - 0.5f);
                q = fminf(fmaxf(q, 0.f), QMAXF);
                dq[i] = q / rs + mn;
            }
        } else {
#pragma unroll
            for (int i = 0; i < 4; i++) dq[i] = mn;
        }

        float acc[16];
#pragma unroll
        for (int j = 0; j < 16; j++) acc[j] = 0.f;
#pragma unroll
        for (int i = 0; i < 4; i++) {
#pragma unroll
            for (int jj = 0; jj < 4; jj++) {
                float4 ww = w[i * 4 + jj];
                acc[jj * 4 + 0] = fmaf(dq[i], ww.x, acc[jj * 4 + 0]);
                acc[jj * 4 + 1] = fmaf(dq[i], ww.y, acc[jj * 4 + 1]);
                acc[jj * 4 + 2] = fmaf(dq[i], ww.z, acc[jj * 4 + 2]);
                acc[jj * 4 + 3] = fmaf(dq[i], ww.w, acc[jj * 4 + 3]);
            }
        }
        reduce_stage<16, 8>(acc, lane);
        reduce_stage<8, 4>(acc, lane);
        reduce_stage<4, 2>(acc, lane);
        reduce_stage<2, 1>(acc, lane);
        float s = acc[0] + __shfl_xor_sync(0xffffffffu, acc[0], 1);
        if ((lane & 1) == 0)
            y[r * 16 + ((lane >> 1) & 15)] = s;
    }
}

// ---------------------------------------------------------------------------
// CSR row-gather SpMM (R9 measured-best) with PDL: preamble (Ws load) runs
// BEFORE cudaGridDependencySynchronize(); all dependent reads after it.
//   EP=1: relu+qdq+@W(16x16) -> y    EP=2: relu+qdq -> y    EP=3: @W3 -> out
// ---------------------------------------------------------------------------
template<int EP>
__global__ void __launch_bounds__(256) k_spmm(
    const float* __restrict__ yin, const float* __restrict__ noise,
    const float* __restrict__ W, float* __restrict__ out)
{
    __shared__ float Ws[16 * 40];
    if (EP == 1) Ws[threadIdx.x] = W[threadIdx.x];
    if (EP == 3) { for (int i = threadIdx.x; i < 640; i += 256) Ws[i] = W[i]; }
    if (EP != 2) __syncthreads();

#if __CUDA_ARCH__ >= 900
    cudaGridDependencySynchronize();     // wait for predecessor's output
#endif

    const int lane  = threadIdx.x & 31;
    const int l     = lane & 15;                       // dim index
    const int half0 = (blockIdx.x * 8 + (threadIdx.x >> 5)) * 2 + (lane >> 4);
    const int nHalf = SPMM_BLOCKS * 16;

    for (int r = half0; r < NN; r += nHalf) {
        int       i = __ldg(&g_off[r]);
        const int e = __ldg(&g_off[r + 1]);
        float acc = 0.f;

        for (; i + 3 < e; i += 4) {
            int2 c0 = __ldg(&g_ecv[i]);
            int2 c1 = __ldg(&g_ecv[i + 1]);
            int2 c2 = __ldg(&g_ecv[i + 2]);
            int2 c3 = __ldg(&g_ecv[i + 3]);
            float y0 = __ldg(&yin[c0.x * 16 + l]);
            float y1 = __ldg(&yin[c1.x * 16 + l]);
            float y2 = __ldg(&yin[c2.x * 16 + l]);
            float y3 = __ldg(&yin[c3.x * 16 + l]);
            acc = fmaf(__int_as_float(c0.y), y0, acc);
            acc = fmaf(__int_as_float(c1.y), y1, acc);
            acc = fmaf(__int_as_float(c2.y), y2, acc);
            acc = fmaf(__int_as_float(c3.y), y3, acc);
        }
        for (; i < e; i++) {
            int2 cv = __ldg(&g_ecv[i]);
            acc = fmaf(__int_as_float(cv.y), __ldg(&yin[cv.x * 16 + l]), acc);
        }

        if (EP == 3) {
            float a0 = 0.f, a1 = 0.f, a2 = 0.f;
#pragma unroll
            for (int j = 0; j < 16; j++) {
                float d = __shfl_sync(0xffffffffu, acc, (lane & 16) + j);
                a0 = fmaf(d, Ws[j * 40 + l], a0);
                a1 = fmaf(d, Ws[j * 40 + l + 16], a1);
                if (l < 8) a2 = fmaf(d, Ws[j * 40 + l + 32], a2);
            }
            out[r * 40 + l]      = a0;
            out[r * 40 + l + 16] = a1;
            if (l < 8) out[r * 40 + l + 32] = a2;
        } else {
            float xr = fmaxf(acc, 0.f);
            float mn = xr, mx = xr;
#pragma unroll
            for (int o = 8; o > 0; o >>= 1) {
                mn = fminf(mn, __shfl_xor_sync(0xffffffffu, mn, o));
                mx = fmaxf(mx, __shfl_xor_sync(0xffffffffu, mx, o));
            }
            float dq;
            if (mx > mn) {
                float rs = QMAXF / (mx - mn);
                float nz = __ldg(&noise[r * 16 + l]);
                float q  = rintf((xr - mn) * rs + nz - 0.5f);
                q = fminf(fmaxf(q, 0.f), QMAXF);
                dq = q / rs + mn;
            } else dq = mn;

            if (EP == 2) {
                out[r * 16 + l] = dq;
            } else {
                float a = 0.f;
#pragma unroll
                for (int j = 0; j < 16; j++) {
                    float d = __shfl_sync(0xffffffffu, dq, (lane & 16) + j);
                    a = fmaf(d, Ws[j * 16 + l], a);
                }
                out[r * 16 + l] = a;
            }
        }
    }
}

// ---------------------------------------------------------------------------
// Launch: fork/join (layer1 on side stream) + PDL on build chain and SpMMs.
// ---------------------------------------------------------------------------
extern "C" void kernel_launch(void* const* d_in, const int* in_sizes, int n_in,
                              void* d_out, int out_size)
{
    const float* features = (const float*)d_in[0];
    const int*   row      = (const int*)  d_in[1];
    const int*   col      = (const int*)  d_in[2];
    const float* vals     = (const float*)d_in[3];
    const float* W1       = (const float*)d_in[4];
    const float* W2       = (const float*)d_in[5];
    const float* W3       = (const float*)d_in[6];
    const float* noise1   = (const float*)d_in[7];
    const float* noise2   = (const float*)d_in[8];
    const float* noise3   = (const float*)d_in[9];

    float *pya, *pyb; int* pcnt;
    cudaGetSymbolAddress((void**)&pya,  g_ya);
    cudaGetSymbolAddress((void**)&pyb,  g_yb);
    cudaGetSymbolAddress((void**)&pcnt, g_cnt);

    const int edgeBlocks = (NE + 255) / 256;     // 6250
    const int scanBlocks = (NN + 1023) / 1024;   // 98

    cudaStream_t s2;
    cudaEvent_t evFork, evJoin;
    cudaStreamCreateWithFlags(&s2, cudaStreamNonBlocking);
    cudaEventCreateWithFlags(&evFork, cudaEventDisableTiming);
    cudaEventCreateWithFlags(&evJoin, cudaEventDisableTiming);

    // Fork: layer1 runs parallel to the CSR build chain.
    cudaEventRecord(evFork, 0);
    cudaStreamWaitEvent(s2, evFork, 0);
    k_layer1<<<740, 128, 0, s2>>>(features, noise1, W1, pya);
    cudaEventRecord(evJoin, s2);

    // PDL launch config helper.
    cudaLaunchAttribute pdlAttr[1];
    pdlAttr[0].id = cudaLaunchAttributeProgrammaticStreamSerialization;
    pdlAttr[0].val.programmaticStreamSerializationAllowed = 1;

    cudaLaunchConfig_t cfg = {};
    cfg.blockDim = dim3(256, 1, 1);
    cfg.dynamicSmemBytes = 0;
    cfg.stream = 0;
    cfg.attrs = pdlAttr;
    cfg.numAttrs = 1;

    // CSR build (default stream). hist = plain launch (after memset node);
    // scan1/scan3/scatter PDL-chained.
    cudaMemsetAsync(pcnt, 0, NN * sizeof(int));
    k_hist<<<edgeBlocks, 256>>>(row);

    cfg.gridDim = dim3(scanBlocks, 1, 1);
    cudaLaunchKernelEx(&cfg, k_scan1);
    cudaLaunchKernelEx(&cfg, k_scan3);

    cfg.gridDim = dim3(edgeBlocks, 1, 1);
    cudaLaunchKernelEx(&cfg, k_scatter, row, col, vals);

    // Join: spmm<1> needs both layer1 output and the CSR.
    cudaStreamWaitEvent(0, evJoin, 0);

    // SpMM pipeline with PDL.
    cfg.gridDim = dim3(SPMM_BLOCKS, 1, 1);
    cudaLaunchKernelEx(&cfg, k_spmm<1>, pya, noise2, W2, pyb);
    cudaLaunchKernelEx(&cfg, k_spmm<2>, pyb, noise3, (const float*)nullptr, pya);
    cudaLaunchKernelEx(&cfg, k_spmm<3>, pya, (const float*)nullptr, W3, (float*)d_out);
}